// round 2
// baseline (speedup 1.0000x reference)
#include <cuda_runtime.h>
#include <math.h>

#define NN      100000
#define EE      1600000
#define ET      (EE + NN)          // edges + self loops = 1,700,000
#define F_IN    128
#define H1DIM   64                  // 8 heads * 8
#define HEADS   8
#define OUT1    8
#define CDIM    40
#define NEG     0.2f

// ---------------- scratch (static device globals; no allocation) -------------
__device__ int   g_rowptr[NN + 1];
__device__ int   g_cursor[NN];
__device__ int   g_csrc[ET];
__device__ float g_h1[NN * H1DIM];
__device__ float g_as1[NN * HEADS];
__device__ float g_ad1[NN * HEADS];
__device__ float g_o1[NN * H1DIM];
__device__ float g_h2[NN * CDIM];
__device__ float g_as2[NN];
__device__ float g_ad2[NN];

// ---------------- CSR build --------------------------------------------------
__global__ void k_zero_counts() {
    int i = blockIdx.x * blockDim.x + threadIdx.x;
    if (i < NN) g_cursor[i] = 0;
}

__global__ void k_count(const int* __restrict__ ei) {
    int e = blockIdx.x * blockDim.x + threadIdx.x;
    if (e >= ET) return;
    int dst = (e < EE) ? ei[EE + e] : (e - EE);
    atomicAdd(&g_cursor[dst], 1);
}

__global__ void k_scan() {
    // single block, 1024 threads; exclusive scan of counts -> rowptr & cursor
    __shared__ int sh[1024];
    const int CHUNK = 98;                 // 1024*98 >= 100000
    int t = threadIdx.x;
    int beg = t * CHUNK;
    int end = min(beg + CHUNK, NN);
    int s = 0;
    for (int i = beg; i < end; i++) s += g_cursor[i];
    sh[t] = s;
    __syncthreads();
    for (int d = 1; d < 1024; d <<= 1) {
        int v = (t >= d) ? sh[t - d] : 0;
        __syncthreads();
        sh[t] += v;
        __syncthreads();
    }
    int off = (t > 0) ? sh[t - 1] : 0;
    for (int i = beg; i < end; i++) {
        int c = g_cursor[i];
        g_rowptr[i] = off;
        g_cursor[i] = off;
        off += c;
    }
    if (t == 1023) g_rowptr[NN] = sh[1023];
}

__global__ void k_scatter(const int* __restrict__ ei) {
    int e = blockIdx.x * blockDim.x + threadIdx.x;
    if (e >= ET) return;
    int src, dst;
    if (e < EE) { src = ei[e]; dst = ei[EE + e]; }
    else        { src = e - EE; dst = e - EE; }
    int pos = atomicAdd(&g_cursor[dst], 1);
    g_csrc[pos] = src;
}

// ---------------- GEMM1: h1 = x @ W1, + alpha_src/alpha_dst epilogue ---------
__global__ void k_gemm1(const float* __restrict__ x, const float* __restrict__ W1,
                        const float* __restrict__ asrc, const float* __restrict__ adst) {
    __shared__ float xs[16][F_IN];
    __shared__ float ws[16][H1DIM];
    int col = threadIdx.x & 63;            // output column 0..63
    int ty  = threadIdx.x >> 6;            // 0..3
    int nodeBase = blockIdx.x * 16;

    for (int i = threadIdx.x; i < 16 * F_IN; i += 256) {
        int r = i >> 7, c = i & 127;
        xs[r][c] = x[(nodeBase + r) * F_IN + c];
    }

    float acc[4] = {0.f, 0.f, 0.f, 0.f};
    for (int kk = 0; kk < F_IN; kk += 16) {
        __syncthreads();
        for (int i = threadIdx.x; i < 16 * H1DIM; i += 256) {
            int r = i >> 6, c = i & 63;
            ws[r][c] = W1[(kk + r) * H1DIM + c];
        }
        __syncthreads();
#pragma unroll
        for (int k = 0; k < 16; k++) {
            float w = ws[k][col];
#pragma unroll
            for (int i = 0; i < 4; i++)
                acc[i] = fmaf(xs[ty * 4 + i][kk + k], w, acc[i]);
        }
    }

    int head = col >> 3;
    int o    = col & 7;
    float a_s = asrc[head * OUT1 + o];
    float a_d = adst[head * OUT1 + o];
#pragma unroll
    for (int i = 0; i < 4; i++) {
        int node = nodeBase + ty * 4 + i;
        g_h1[node * H1DIM + col] = acc[i];
        float vs = acc[i] * a_s;
        float vd = acc[i] * a_d;
#pragma unroll
        for (int d = 1; d < 8; d <<= 1) {
            vs += __shfl_xor_sync(0xffffffffu, vs, d);
            vd += __shfl_xor_sync(0xffffffffu, vd, d);
        }
        if (o == 0) {
            g_as1[node * HEADS + head] = vs;
            g_ad1[node * HEADS + head] = vd;
        }
    }
}

// ------- layer-1 aggregation: per-dst ONLINE softmax (single pass) ----------
__global__ void k_agg1(const float* __restrict__ b1) {
    int node = blockIdx.x * 4 + (threadIdx.x >> 6);
    if (node >= NN) return;
    int lane = threadIdx.x & 63;           // channel
    int head = lane >> 3;

    int beg = g_rowptr[node];
    int end = g_rowptr[node + 1];
    float ad = g_ad1[node * HEADS + head];

    float m = -INFINITY, den = 0.f, acc = 0.f;
#pragma unroll 4
    for (int i = beg; i < end; i++) {
        int s = g_csrc[i];
        float e = g_as1[s * HEADS + head] + ad;
        e = (e > 0.f) ? e : NEG * e;
        float hv = g_h1[s * H1DIM + lane];
        float mn = fmaxf(m, e);
        float sc = __expf(m - mn);
        float w  = __expf(e - mn);
        den = den * sc + w;
        acc = fmaf(acc, sc, w * hv);
        m = mn;
    }

    float out = acc / den + b1[lane];
    g_o1[node * H1DIM + lane] = (out > 0.f) ? out : NEG * out;   // fused leaky_relu
}

// ---------------- GEMM2: h2 = o1 @ W2, + alpha2 epilogue ---------------------
__global__ void k_gemm2(const float* __restrict__ W2,
                        const float* __restrict__ asrc2, const float* __restrict__ adst2) {
    __shared__ float os[8][H1DIM];
    __shared__ float ws[H1DIM * CDIM];
    __shared__ float shs[8][CDIM];
    __shared__ float shd[8][CDIM];
    int tid = threadIdx.x;                 // 0..319
    int r   = tid / CDIM;                  // node within block 0..7
    int col = tid % CDIM;                  // class 0..39
    int nodeBase = blockIdx.x * 8;

    for (int i = tid; i < 8 * H1DIM; i += 320) {
        int rr = i >> 6, c = i & 63;
        os[rr][c] = g_o1[(nodeBase + rr) * H1DIM + c];
    }
    for (int i = tid; i < H1DIM * CDIM; i += 320) ws[i] = W2[i];
    __syncthreads();

    float acc = 0.f;
#pragma unroll 8
    for (int k = 0; k < H1DIM; k++)
        acc = fmaf(os[r][k], ws[k * CDIM + col], acc);

    int node = nodeBase + r;
    g_h2[node * CDIM + col] = acc;
    shs[r][col] = acc * asrc2[col];
    shd[r][col] = acc * adst2[col];
    __syncthreads();
    if (tid < 8) {
        float ss = 0.f, sd = 0.f;
#pragma unroll 8
        for (int c = 0; c < CDIM; c++) { ss += shs[tid][c]; sd += shd[tid][c]; }
        g_as2[nodeBase + tid] = ss;
        g_ad2[nodeBase + tid] = sd;
    }
}

// ------- layer-2 aggregation (online softmax) -> logits ---------------------
__global__ void k_agg2(const float* __restrict__ b2, float* __restrict__ out) {
    int node = blockIdx.x * 4 + (threadIdx.x >> 6);
    if (node >= NN) return;
    int lane = threadIdx.x & 63;

    int beg = g_rowptr[node];
    int end = g_rowptr[node + 1];
    float ad = g_ad2[node];

    float m = -INFINITY, den = 0.f, acc = 0.f;
#pragma unroll 4
    for (int i = beg; i < end; i++) {
        int s = g_csrc[i];
        float e = g_as2[s] + ad;
        e = (e > 0.f) ? e : NEG * e;
        float hv = (lane < CDIM) ? g_h2[s * CDIM + lane] : 0.f;
        float mn = fmaxf(m, e);
        float sc = __expf(m - mn);
        float w  = __expf(e - mn);
        den = den * sc + w;
        acc = fmaf(acc, sc, w * hv);
        m = mn;
    }

    if (lane < CDIM)
        out[node * CDIM + lane] = acc / den + b2[lane];
}

// ---------------- row-wise log_softmax (in-place on d_out) -------------------
__global__ void k_lsm(float* __restrict__ out) {
    int warp = threadIdx.x >> 5;
    int lane = threadIdx.x & 31;
    int node = blockIdx.x * 8 + warp;
    if (node >= NN) return;

    float v0 = out[node * CDIM + lane];                 // lanes 0..31 -> c 0..31
    float v1 = (lane < 8) ? out[node * CDIM + 32 + lane] : -INFINITY;

    float m = fmaxf(v0, v1);
#pragma unroll
    for (int d = 16; d >= 1; d >>= 1)
        m = fmaxf(m, __shfl_xor_sync(0xffffffffu, m, d));

    float s = expf(v0 - m) + ((lane < 8) ? expf(v1 - m) : 0.f);
#pragma unroll
    for (int d = 16; d >= 1; d >>= 1)
        s += __shfl_xor_sync(0xffffffffu, s, d);

    float l = m + logf(s);
    out[node * CDIM + lane] = v0 - l;
    if (lane < 8) out[node * CDIM + 32 + lane] = v1 - l;
}

// ---------------- launch ----------------------------------------------------
extern "C" void kernel_launch(void* const* d_in, const int* in_sizes, int n_in,
                              void* d_out, int out_size) {
    const float* x        = (const float*)d_in[0];
    const int*   ei       = (const int*)  d_in[1];
    const float* W1       = (const float*)d_in[2];
    const float* att_src1 = (const float*)d_in[3];
    const float* att_dst1 = (const float*)d_in[4];
    const float* b1       = (const float*)d_in[5];
    const float* W2       = (const float*)d_in[6];
    const float* att_src2 = (const float*)d_in[7];
    const float* att_dst2 = (const float*)d_in[8];
    const float* b2       = (const float*)d_in[9];
    float* out = (float*)d_out;

    // CSR build (dst-grouped)
    k_zero_counts<<<(NN + 255) / 256, 256>>>();
    k_count<<<(ET + 255) / 256, 256>>>(ei);
    k_scan<<<1, 1024>>>();
    k_scatter<<<(ET + 255) / 256, 256>>>(ei);

    // layer 1
    k_gemm1<<<NN / 16, 256>>>(x, W1, att_src1, att_dst1);
    k_agg1<<<(NN + 3) / 4, 256>>>(b1);

    // layer 2
    k_gemm2<<<NN / 8, 320>>>(W2, att_src2, att_dst2);
    k_agg2<<<(NN + 3) / 4, 256>>>(b2, out);

    // log_softmax
    k_lsm<<<(NN + 7) / 8, 256>>>(out);
}

// round 3
// speedup vs baseline: 1.1823x; 1.1823x over previous
#include <cuda_runtime.h>
#include <math.h>

#define NN      100000
#define EE      1600000
#define ET      (EE + NN)          // edges + self loops = 1,700,000
#define F_IN    128
#define H1DIM   64                  // 8 heads * 8
#define HEADS   8
#define OUT1    8
#define CDIM    40
#define NEG     0.2f

// ---------------- scratch (static device globals; no allocation) -------------
__device__ int   g_rowptr[NN + 1];
__device__ int   g_cursor[NN];
__device__ int   g_csrc[ET];
__device__ float g_h1[NN * H1DIM];
__device__ float g_as1[NN * HEADS];
__device__ float g_ad1[NN * HEADS];
__device__ float g_o1[NN * H1DIM];
__device__ float g_h2[NN * CDIM];
__device__ float g_as2[NN];
__device__ float g_ad2[NN];

// ---------------- CSR build --------------------------------------------------
__global__ void k_zero_counts() {
    int i = blockIdx.x * blockDim.x + threadIdx.x;
    if (i < NN) g_cursor[i] = 0;
}

__global__ void k_count(const int* __restrict__ ei) {
    int e = blockIdx.x * blockDim.x + threadIdx.x;
    if (e >= ET) return;
    int dst = (e < EE) ? ei[EE + e] : (e - EE);
    atomicAdd(&g_cursor[dst], 1);
}

__global__ void k_scan() {
    // single block, 1024 threads; exclusive scan of counts -> rowptr & cursor
    __shared__ int sh[1024];
    const int CHUNK = 98;                 // 1024*98 >= 100000
    int t = threadIdx.x;
    int beg = t * CHUNK;
    int end = min(beg + CHUNK, NN);
    int s = 0;
    for (int i = beg; i < end; i++) s += g_cursor[i];
    sh[t] = s;
    __syncthreads();
    for (int d = 1; d < 1024; d <<= 1) {
        int v = (t >= d) ? sh[t - d] : 0;
        __syncthreads();
        sh[t] += v;
        __syncthreads();
    }
    int off = (t > 0) ? sh[t - 1] : 0;
    for (int i = beg; i < end; i++) {
        int c = g_cursor[i];
        g_rowptr[i] = off;
        g_cursor[i] = off;
        off += c;
    }
    if (t == 1023) g_rowptr[NN] = sh[1023];
}

__global__ void k_scatter(const int* __restrict__ ei) {
    int e = blockIdx.x * blockDim.x + threadIdx.x;
    if (e >= ET) return;
    int src, dst;
    if (e < EE) { src = ei[e]; dst = ei[EE + e]; }
    else        { src = e - EE; dst = e - EE; }
    int pos = atomicAdd(&g_cursor[dst], 1);
    g_csrc[pos] = src;
}

// ---------------- GEMM1: h1 = x @ W1, + alpha_src/alpha_dst epilogue ---------
__global__ void k_gemm1(const float* __restrict__ x, const float* __restrict__ W1,
                        const float* __restrict__ asrc, const float* __restrict__ adst) {
    __shared__ float xs[16][F_IN];
    __shared__ float ws[F_IN][H1DIM];      // full W1: 32 KB
    int col = threadIdx.x & 63;            // output column 0..63
    int ty  = threadIdx.x >> 6;            // 0..3
    int nodeBase = blockIdx.x * 16;

    for (int i = threadIdx.x; i < 16 * F_IN; i += 256) {
        int r = i >> 7, c = i & 127;
        xs[r][c] = x[(nodeBase + r) * F_IN + c];
    }
    for (int i = threadIdx.x; i < F_IN * H1DIM; i += 256) {
        ws[i >> 6][i & 63] = W1[i];
    }
    __syncthreads();

    float acc[4] = {0.f, 0.f, 0.f, 0.f};
#pragma unroll 16
    for (int k = 0; k < F_IN; k++) {
        float w = ws[k][col];
#pragma unroll
        for (int i = 0; i < 4; i++)
            acc[i] = fmaf(xs[ty * 4 + i][k], w, acc[i]);
    }

    int head = col >> 3;
    int o    = col & 7;
    float a_s = asrc[head * OUT1 + o];
    float a_d = adst[head * OUT1 + o];
#pragma unroll
    for (int i = 0; i < 4; i++) {
        int node = nodeBase + ty * 4 + i;
        g_h1[node * H1DIM + col] = acc[i];
        float vs = acc[i] * a_s;
        float vd = acc[i] * a_d;
#pragma unroll
        for (int d = 1; d < 8; d <<= 1) {
            vs += __shfl_xor_sync(0xffffffffu, vs, d);
            vd += __shfl_xor_sync(0xffffffffu, vd, d);
        }
        if (o == 0) {
            g_as1[node * HEADS + head] = vs;
            g_ad1[node * HEADS + head] = vd;
        }
    }
}

// ------- layer-1 aggregation: warp per node, two-pass softmax, float2 -------
__global__ void k_agg1(const float* __restrict__ b1) {
    int warp = threadIdx.x >> 5;
    int lane = threadIdx.x & 31;
    int node = blockIdx.x * 8 + warp;
    if (node >= NN) return;
    int head = lane >> 2;                  // channels 2*lane, 2*lane+1 -> head

    int beg = __ldg(&g_rowptr[node]);
    int end = __ldg(&g_rowptr[node + 1]);
    float ad = __ldg(&g_ad1[node * HEADS + head]);

    // pass 1: max (independent loads, 4-cyc fmax carry)
    float m = -INFINITY;
#pragma unroll 8
    for (int i = beg; i < end; i++) {
        int s = __ldg(&g_csrc[i]);
        float e = __ldg(&g_as1[s * HEADS + head]) + ad;
        e = (e > 0.f) ? e : NEG * e;
        m = fmaxf(m, e);
    }

    // pass 2: exp-weighted gather, exp off the load-dep path
    const float2* h1v = (const float2*)g_h1;
    float den = 0.f;
    float2 acc = make_float2(0.f, 0.f);
#pragma unroll 4
    for (int i = beg; i < end; i++) {
        int s = __ldg(&g_csrc[i]);
        float e = __ldg(&g_as1[s * HEADS + head]) + ad;
        e = (e > 0.f) ? e : NEG * e;
        float w = __expf(e - m);
        float2 hv = __ldg(&h1v[s * 32 + lane]);
        den += w;
        acc.x = fmaf(w, hv.x, acc.x);
        acc.y = fmaf(w, hv.y, acc.y);
    }

    float inv = __frcp_rn(den);
    float ox = fmaf(acc.x, inv, 0.f) + __ldg(&b1[2 * lane]);
    float oy = fmaf(acc.y, inv, 0.f) + __ldg(&b1[2 * lane + 1]);
    ox = (ox > 0.f) ? ox : NEG * ox;       // fused leaky_relu
    oy = (oy > 0.f) ? oy : NEG * oy;
    ((float2*)g_o1)[node * 32 + lane] = make_float2(ox, oy);
}

// ---------------- GEMM2: h2 = o1 @ W2, + alpha2 epilogue ---------------------
__global__ void k_gemm2(const float* __restrict__ W2,
                        const float* __restrict__ asrc2, const float* __restrict__ adst2) {
    __shared__ float os[8][H1DIM];
    __shared__ float ws[H1DIM * CDIM];
    __shared__ float shs[8][CDIM];
    __shared__ float shd[8][CDIM];
    int tid = threadIdx.x;                 // 0..319
    int r   = tid / CDIM;                  // node within block 0..7
    int col = tid % CDIM;                  // class 0..39
    int nodeBase = blockIdx.x * 8;

    for (int i = tid; i < 8 * H1DIM; i += 320) {
        int rr = i >> 6, c = i & 63;
        os[rr][c] = g_o1[(nodeBase + rr) * H1DIM + c];
    }
    for (int i = tid; i < H1DIM * CDIM; i += 320) ws[i] = W2[i];
    __syncthreads();

    float acc = 0.f;
#pragma unroll 8
    for (int k = 0; k < H1DIM; k++)
        acc = fmaf(os[r][k], ws[k * CDIM + col], acc);

    int node = nodeBase + r;
    g_h2[node * CDIM + col] = acc;
    shs[r][col] = acc * asrc2[col];
    shd[r][col] = acc * adst2[col];
    __syncthreads();
    if (tid < 8) {
        float ss = 0.f, sd = 0.f;
#pragma unroll 8
        for (int c = 0; c < CDIM; c++) { ss += shs[tid][c]; sd += shd[tid][c]; }
        g_as2[nodeBase + tid] = ss;
        g_ad2[nodeBase + tid] = sd;
    }
}

// ------- layer-2 aggregation: warp per node, two-pass softmax ---------------
__global__ void k_agg2(const float* __restrict__ b2, float* __restrict__ out) {
    int warp = threadIdx.x >> 5;
    int lane = threadIdx.x & 31;
    int node = blockIdx.x * 8 + warp;
    if (node >= NN) return;

    int beg = __ldg(&g_rowptr[node]);
    int end = __ldg(&g_rowptr[node + 1]);
    float ad = __ldg(&g_ad2[node]);

    float m = -INFINITY;
#pragma unroll 8
    for (int i = beg; i < end; i++) {
        int s = __ldg(&g_csrc[i]);
        float e = __ldg(&g_as2[s]) + ad;
        e = (e > 0.f) ? e : NEG * e;
        m = fmaxf(m, e);
    }

    const float2* h2v = (const float2*)g_h2;   // 20 float2 per node
    float den = 0.f;
    float2 acc = make_float2(0.f, 0.f);
#pragma unroll 4
    for (int i = beg; i < end; i++) {
        int s = __ldg(&g_csrc[i]);
        float e = __ldg(&g_as2[s]) + ad;
        e = (e > 0.f) ? e : NEG * e;
        float w = __expf(e - m);
        den += w;
        if (lane < 20) {
            float2 hv = __ldg(&h2v[s * 20 + lane]);
            acc.x = fmaf(w, hv.x, acc.x);
            acc.y = fmaf(w, hv.y, acc.y);
        }
    }

    if (lane < 20) {
        float inv = __frcp_rn(den);
        float2 o;
        o.x = acc.x * inv + __ldg(&b2[2 * lane]);
        o.y = acc.y * inv + __ldg(&b2[2 * lane + 1]);
        ((float2*)out)[node * 20 + lane] = o;
    }
}

// ---------------- row-wise log_softmax (in-place on d_out) -------------------
__global__ void k_lsm(float* __restrict__ out) {
    int warp = threadIdx.x >> 5;
    int lane = threadIdx.x & 31;
    int node = blockIdx.x * 8 + warp;
    if (node >= NN) return;

    float v0 = out[node * CDIM + lane];                 // lanes 0..31 -> c 0..31
    float v1 = (lane < 8) ? out[node * CDIM + 32 + lane] : -INFINITY;

    float m = fmaxf(v0, v1);
#pragma unroll
    for (int d = 16; d >= 1; d >>= 1)
        m = fmaxf(m, __shfl_xor_sync(0xffffffffu, m, d));

    float s = expf(v0 - m) + ((lane < 8) ? expf(v1 - m) : 0.f);
#pragma unroll
    for (int d = 16; d >= 1; d >>= 1)
        s += __shfl_xor_sync(0xffffffffu, s, d);

    float l = m + logf(s);
    out[node * CDIM + lane] = v0 - l;
    if (lane < 8) out[node * CDIM + 32 + lane] = v1 - l;
}

// ---------------- launch ----------------------------------------------------
extern "C" void kernel_launch(void* const* d_in, const int* in_sizes, int n_in,
                              void* d_out, int out_size) {
    const float* x        = (const float*)d_in[0];
    const int*   ei       = (const int*)  d_in[1];
    const float* W1       = (const float*)d_in[2];
    const float* att_src1 = (const float*)d_in[3];
    const float* att_dst1 = (const float*)d_in[4];
    const float* b1       = (const float*)d_in[5];
    const float* W2       = (const float*)d_in[6];
    const float* att_src2 = (const float*)d_in[7];
    const float* att_dst2 = (const float*)d_in[8];
    const float* b2       = (const float*)d_in[9];
    float* out = (float*)d_out;

    // CSR build (dst-grouped)
    k_zero_counts<<<(NN + 255) / 256, 256>>>();
    k_count<<<(ET + 255) / 256, 256>>>(ei);
    k_scan<<<1, 1024>>>();
    k_scatter<<<(ET + 255) / 256, 256>>>(ei);

    // layer 1
    k_gemm1<<<NN / 16, 256>>>(x, W1, att_src1, att_dst1);
    k_agg1<<<(NN + 7) / 8, 256>>>(b1);

    // layer 2
    k_gemm2<<<NN / 8, 320>>>(W2, att_src2, att_dst2);
    k_agg2<<<(NN + 7) / 8, 256>>>(b2, out);

    // log_softmax
    k_lsm<<<(NN + 7) / 8, 256>>>(out);
}